// round 13
// baseline (speedup 1.0000x reference)
#include <cuda_runtime.h>
#include <math.h>

// R13 == R12 resubmission: round-12 bench died with the same infra-level
// container failure seen in round 5 (which reran cleanly). Kernel audited:
// all 128 blocks execute the same 10 gsync()s, W23 jobs cover exactly 3075
// with no OOB, Phase-M edge split covers exactly 90112 edges. No hang path.

#define F      16
#define E0C    90112
#define N0C    1408
#define GRID   128
#define BLOCK  512
#define NT     (GRID * BLOCK)
#define CAP3   2560

// ---------------- persistent device state ----------------
__device__ unsigned int g_arrive;
__device__ unsigned int g_gen;             // monotonic generation
__device__ int g_c1, g_c2;                 // compacted edge counts (layers 1,2)
__device__ __align__(16) float g_h   [N0C * F];   // conv input h = x@W (per layer)
__device__ __align__(16) float g_outA[N0C * F];   // O_0, then reused as O_2
__device__ __align__(16) float g_outB[704 * F];   // O_1
__device__ __align__(16) float g_out3[176 * F];   // O_3
__device__ float g_deg0[N0C];
__device__ float g_deg1[704];
__device__ float g_deg2[352];
__device__ int   g_pos [N0C];              // old -> new (or -1), layers 0,1
__device__ int2  g_e0[E0C];
__device__ int2  g_e1[E0C];
__device__ int2  g_e2[E0C];
__device__ float g_h1[1025];               // fc1 output + virtual 1.0 entry
__device__ float g_W23[1025 * 96];         // fused fw2@fw3 (+ fb2@fw3 as row 1024)

// ---------------- flat grid barrier (R4-proven) ----------------
__device__ __forceinline__ void gsync() {
    __syncthreads();
    if (threadIdx.x == 0) {
        unsigned int gen;
        asm volatile("ld.acquire.gpu.u32 %0, [%1];" : "=r"(gen) : "l"(&g_gen) : "memory");
        unsigned int old;
        asm volatile("atom.add.release.gpu.u32 %0, [%1], 1;"
                     : "=r"(old) : "l"(&g_arrive) : "memory");
        if (old == GRID - 1u) {
            asm volatile("st.relaxed.gpu.u32 [%0], 0;" :: "l"(&g_arrive) : "memory");
            asm volatile("st.release.gpu.u32 [%0], %1;" :: "l"(&g_gen), "r"(gen + 1u) : "memory");
        } else {
            unsigned int cur;
            do {
                asm volatile("ld.acquire.gpu.u32 %0, [%1];" : "=r"(cur) : "l"(&g_gen) : "memory");
            } while (cur == gen);
        }
    }
    __syncthreads();
}

__device__ __forceinline__ void red_add_v4(float* addr, float a, float b, float c, float d) {
    asm volatile("red.global.add.v4.f32 [%0], {%1, %2, %3, %4};"
                 :: "l"(addr), "f"(a), "f"(b), "f"(c), "f"(d) : "memory");
}

__device__ __forceinline__ unsigned long long score_key(const float* __restrict__ outL,
                                                        const float* __restrict__ bb,
                                                        const float* __restrict__ pw,
                                                        float npw, int i) {
    float s = 0.0f;
    #pragma unroll
    for (int f = 0; f < F; f++) {
        float v = outL[i * F + f] + bb[f];
        v = v > 0.0f ? v : 0.0f;
        s += v * pw[f];
    }
    float sc = tanhf(s / npw);
    int bits = __float_as_int(sc);
    unsigned int ka = (bits >= 0) ? (0x80000000u + (unsigned int)bits)
                                  : ~(unsigned int)bits;
    return ((unsigned long long)(~ka) << 32) | (unsigned int)i;
}

__device__ __forceinline__ float key_val(unsigned long long key) {
    unsigned int ka = ~(unsigned int)(key >> 32);
    int bits = (ka >= 0x80000000u) ? (int)(ka - 0x80000000u) : (int)(~ka);
    return __int_as_float(bits);
}

__device__ __forceinline__ float pw_norm(const float* __restrict__ pw) {
    float npw = 0.0f;
    #pragma unroll
    for (int f = 0; f < F; f++) { float v = pw[f]; npw += v * v; }
    return sqrtf(npw);
}

// W23 warp-job: job < 3075; row = job/3 (1024 = fb2 virtual row); 32 cols per job
__device__ __forceinline__ void w23_job(int job, int lane,
                                        const float* __restrict__ fw2,
                                        const float* __restrict__ fb2,
                                        const float* __restrict__ fw3) {
    if (job >= 3075) return;
    int row = job / 3;
    int jc  = (job % 3) * 32 + lane;
    const float* src = (row < 1024) ? (fw2 + row * 512) : fb2;
    float acc = 0.0f;
    #pragma unroll 8
    for (int k = 0; k < 512; k++) acc += src[k] * fw3[k * 96 + jc];
    g_W23[row * 96 + jc] = acc;
}

// distributed scatter: self-loops + edges, RED into global accum
__device__ __forceinline__ void scatter_g(const float* __restrict__ h,
                                          const int2* __restrict__ el, int C,
                                          const float* __restrict__ deg,
                                          float* __restrict__ ob, int n, int gtid) {
    for (int t = gtid; t < n + C; t += NT) {
        const float4* hr; float* oc; float norm;
        if (t < n) {
            norm = 1.0f / (deg[t] + 1.0f);
            hr = (const float4*)&h[t * F]; oc = &ob[t * F];
        } else {
            int2 rc = el[t - n];
            norm = __frsqrt_rn(deg[rc.x] + 1.0f) * __frsqrt_rn(deg[rc.y] + 1.0f);
            hr = (const float4*)&h[rc.x * F]; oc = &ob[rc.y * F];
        }
        #pragma unroll
        for (int q = 0; q < 4; q++) {
            float4 hv = hr[q];
            red_add_v4(oc + 4 * q, norm * hv.x, norm * hv.y, norm * hv.z, norm * hv.w);
        }
    }
}

// distributed pool: rank own warp's node, fused gather+gemm into hdst, zero outN
__device__ __forceinline__ void pool_dist(const float* __restrict__ outL,
                                          const float* __restrict__ bb,
                                          const float* __restrict__ pw,
                                          const float* __restrict__ Wn,
                                          float* __restrict__ outN,
                                          float* __restrict__ hdst,
                                          int n, int K,
                                          unsigned long long* s_keys,
                                          int tid, int lane, int wid, int bx) {
    float npw = pw_norm(pw);
    for (int i = tid; i < n; i += BLOCK) s_keys[i] = score_key(outL, bb, pw, npw, i);
    __syncthreads();
    int i = bx * (BLOCK / 32) + wid;
    if (i < n) {
        unsigned long long ki = s_keys[i];
        int cnt = 0;
        for (int j = lane; j < n; j += 32) cnt += (s_keys[j] < ki) ? 1 : 0;
        int rank = __reduce_add_sync(0xFFFFFFFFu, cnt);
        if (rank < K) {
            float val = key_val(ki);
            if (lane == 0) g_pos[i] = rank;
            if (lane < F) {
                float acc = 0.0f;
                #pragma unroll
                for (int f = 0; f < F; f++) {
                    float v = outL[i * F + f] + bb[f];
                    v = v > 0.0f ? v : 0.0f;
                    acc += v * Wn[f * F + lane];
                }
                hdst[rank * F + lane] = acc * val;
                outN[rank * F + lane] = 0.0f;
            }
        } else if (lane == 0) {
            g_pos[i] = -1;
        }
    }
    __syncthreads();
}

// distributed edge remap + compact + degree
__device__ __forceinline__ void remap_dist(const int2* __restrict__ ein, int C,
                                           int2* __restrict__ eout, int* pcnt,
                                           float* __restrict__ degout,
                                           int gtid, int lane) {
    int iters = (C + NT - 1) / NT;
    for (int it = 0; it < iters; it++) {
        int e = it * NT + gtid;
        bool valid = false; int nr = 0, nc = 0;
        if (e < C) {
            int2 rc = ein[e];
            nr = g_pos[rc.x]; nc = g_pos[rc.y];
            valid = (nr >= 0) && (nc >= 0);
        }
        unsigned int m = __ballot_sync(0xFFFFFFFFu, valid);
        if (m) {
            int leader = __ffs(m) - 1;
            int base = 0;
            if (lane == leader) base = atomicAdd(pcnt, __popc(m));
            base = __shfl_sync(0xFFFFFFFFu, base, leader);
            if (valid) {
                int pp = base + __popc(m & ((1u << lane) - 1u));
                eout[pp] = make_int2(nr, nc);
                atomicAdd(&degout[nc], 1.0f);
            }
        }
    }
}

__global__ void __launch_bounds__(BLOCK, 1) gcn_fused(
    const float* __restrict__ x, const int* __restrict__ ei,
    const float* __restrict__ W0, const float* __restrict__ b0,
    const float* __restrict__ W1, const float* __restrict__ b1,
    const float* __restrict__ W2, const float* __restrict__ b2,
    const float* __restrict__ W3, const float* __restrict__ b3,
    const float* __restrict__ pw0, const float* __restrict__ pw1,
    const float* __restrict__ pw2, const float* __restrict__ pw3,
    const float* __restrict__ fw1, const float* __restrict__ fb1,
    const float* __restrict__ fw2, const float* __restrict__ fb2,
    const float* __restrict__ fw3, const float* __restrict__ fb3,
    float* __restrict__ out)
{
    const int tid  = threadIdx.x;
    const int gtid = blockIdx.x * BLOCK + tid;
    const int lane = tid & 31;
    const int wid  = tid >> 5;
    const int bx   = blockIdx.x;

    __shared__ __align__(16) unsigned long long s_keys[N0C];  // 11.3 KB
    __shared__ __align__(16) float s_h3[176 * F];             // 11.3 KB
    __shared__ unsigned int s_e3[CAP3];                       // 10.2 KB
    __shared__ short  s_pos2[352];
    __shared__ short  s_perm[176];
    __shared__ float  s_val [176];
    __shared__ float  s_deg3[176];
    __shared__ int    s_scan[17];

    // ================= Phase M (balanced gemm/edge split) =================
    if (gtid < N0C * F) {             // 22528 gemm tasks, one per thread
        int i = gtid >> 4, j = gtid & 15;
        const float* xr = x + i * 128;
        float acc = 0.0f;
        #pragma unroll 16
        for (int k = 0; k < 128; k++) acc += xr[k] * W0[k * F + j];
        g_h[gtid] = acc;
        g_outA[gtid] = 0.0f;
    }
    {   // edges: threads >= 22528 take 2 each; threads < 4096 take the 4096-edge tail
        if (gtid >= N0C * F) {
            int e = 2 * (gtid - N0C * F);
            #pragma unroll
            for (int q = 0; q < 2; q++) {
                int r = ei[e + q], c = ei[E0C + e + q];
                g_e0[e + q] = make_int2(r, c);
                atomicAdd(&g_deg0[c], 1.0f);
            }
        } else if (gtid < 4096) {
            int e = 2 * (NT - N0C * F) + gtid;   // 86016 + gtid
            int r = ei[e], c = ei[E0C + e];
            g_e0[e] = make_int2(r, c);
            atomicAdd(&g_deg0[c], 1.0f);
        }
    }
    if (gtid < 1024) g_h1[gtid] = fb1[gtid];
    if (gtid == 1024) g_h1[1024] = 1.0f;        // virtual input for fb2 row of W23
    if (gtid < 96)   out[gtid]  = fb3[gtid];
    if (gtid == 0) { g_c1 = 0; g_c2 = 0; }
    gsync();

    // ================= S0 =================
    scatter_g(g_h, g_e0, E0C, g_deg0, g_outA, N0C, gtid);
    gsync();

    // ================= P0 (+ clean deg0; idle blocks compute W23 part 1) =================
    for (int i = gtid; i < N0C; i += NT) g_deg0[i] = 0.0f;
    if (bx < 88) {
        pool_dist(g_outA, b0, pw0, W1, g_outB, g_h, N0C, 704, s_keys, tid, lane, wid, bx);
    } else {
        int widx = (bx - 88) * 16 + wid;       // 0..639
        w23_job(widx * 2,     lane, fw2, fb2, fw3);
        w23_job(widx * 2 + 1, lane, fw2, fb2, fw3);
    }
    gsync();

    // ================= E0 =================
    remap_dist(g_e0, E0C, g_e1, &g_c1, g_deg1, gtid, lane);
    gsync();

    // ================= S1 =================
    {
        int C1 = g_c1;
        scatter_g(g_h, g_e1, C1, g_deg1, g_outB, 704, gtid);
    }
    gsync();

    // ================= P1 (+ clean deg1; idle blocks compute W23 part 2) =================
    for (int i = gtid; i < 704; i += NT) g_deg1[i] = 0.0f;
    if (bx < 44) {
        pool_dist(g_outB, b1, pw1, W2, g_outA, g_h, 704, 352, s_keys, tid, lane, wid, bx);
    } else {
        int widx = (bx - 44) * 16 + wid;       // 0..1343
        w23_job(1280 + widx, lane, fw2, fb2, fw3);
        if (widx < 451) w23_job(2624 + widx, lane, fw2, fb2, fw3);
    }
    gsync();

    // ================= E1 =================
    {
        int C1 = g_c1;
        remap_dist(g_e1, C1, g_e2, &g_c2, g_deg2, gtid, lane);
    }
    gsync();

    // ================= S2 (+ zero O3) =================
    {
        int C2 = g_c2;
        scatter_g(g_h, g_e2, C2, g_deg2, g_outA, 352, gtid);
        if (gtid < 176 * F) g_out3[gtid] = 0.0f;
    }
    gsync();

    // ================= merged P2+E2+S3 (fully redundant per block) =================
    {
        for (int i = gtid; i < 352; i += NT) g_deg2[i] = 0.0f;   // self-clean

        // a) rank all 352 nodes locally
        float npw = pw_norm(pw2);
        for (int i = tid; i < 352; i += BLOCK)
            s_keys[i] = score_key(g_outA, b2, pw2, npw, i);
        if (tid < 176) s_deg3[tid] = 0.0f;
        __syncthreads();
        for (int i = wid; i < 352; i += 16) {
            unsigned long long ki = s_keys[i];
            int cnt = 0;
            for (int j = lane; j < 352; j += 32) cnt += (s_keys[j] < ki) ? 1 : 0;
            int rank = __reduce_add_sync(0xFFFFFFFFu, cnt);
            if (lane == 0) {
                if (rank < 176) {
                    s_pos2[i] = (short)rank;
                    s_perm[rank] = (short)i;
                    s_val[rank] = key_val(ki);
                } else s_pos2[i] = -1;
            }
        }
        __syncthreads();

        // b) deterministic two-pass compaction of g_e2 -> s_e3
        int C2 = g_c2;
        int seg = (C2 + BLOCK - 1) / BLOCK;
        int e0 = tid * seg, e1 = min(e0 + seg, C2);
        int mycnt = 0;
        for (int e = e0; e < e1; e++) {
            int2 rc = g_e2[e];
            if (s_pos2[rc.x] >= 0 && s_pos2[rc.y] >= 0) mycnt++;
        }
        int pre = mycnt;
        #pragma unroll
        for (int d = 1; d < 32; d <<= 1) {
            int t = __shfl_up_sync(0xFFFFFFFFu, pre, d);
            if (lane >= d) pre += t;
        }
        if (lane == 31) s_scan[wid] = pre;
        __syncthreads();
        if (tid == 0) {
            int acc = 0;
            #pragma unroll
            for (int w = 0; w < 16; w++) { int t = s_scan[w]; s_scan[w] = acc; acc += t; }
            s_scan[16] = acc;
        }
        __syncthreads();
        int base = s_scan[wid] + (pre - mycnt);
        int C3 = min(s_scan[16], CAP3);
        for (int e = e0; e < e1; e++) {
            int2 rc = g_e2[e];
            short nr = s_pos2[rc.x], nc = s_pos2[rc.y];
            if (nr >= 0 && nc >= 0) {
                if (base < CAP3)
                    s_e3[base] = (unsigned int)(unsigned short)nr |
                                 ((unsigned int)(unsigned short)nc << 16);
                atomicAdd(&s_deg3[nc], 1.0f);
                base++;
            }
        }
        __syncthreads();

        // c) h3 = X2 @ W3 (warp shfl-gemm) into smem
        {
            float w[16];
            int f2 = lane & 15;
            #pragma unroll
            for (int f = 0; f < 16; f++) w[f] = W3[f * F + f2];
            int sub = lane >> 4;
            for (int j0 = wid * 2; j0 < 176; j0 += 32) {
                int j = j0 + sub;
                int p = s_perm[j];
                float val = s_val[j];
                int f = lane & 15;
                float v = g_outA[p * F + f] + b2[f];
                v = v > 0.0f ? v : 0.0f;
                float acc = 0.0f;
                #pragma unroll
                for (int fk = 0; fk < 16; fk++)
                    acc += __shfl_sync(0xFFFFFFFFu, v, (sub << 4) + fk) * w[fk];
                s_h3[j * F + f2] = acc * val;
            }
        }
        __syncthreads();

        // d) scatter this block's slice (thread-partitioned) into global O3
        {
            int total = 176 + C3;
            int chunk = (total + GRID - 1) / GRID;
            int t0 = bx * chunk, t1 = min(t0 + chunk, total);
            for (int t = t0 + tid; t < t1; t += BLOCK) {
                const float4* hr; float* oc; float norm;
                if (t < 176) {
                    norm = 1.0f / (s_deg3[t] + 1.0f);
                    hr = (const float4*)&s_h3[t * F]; oc = &g_out3[t * F];
                } else {
                    unsigned int pk = s_e3[t - 176];
                    int r = pk & 0xFFFF, c = pk >> 16;
                    norm = __frsqrt_rn(s_deg3[r] + 1.0f) * __frsqrt_rn(s_deg3[c] + 1.0f);
                    hr = (const float4*)&s_h3[r * F]; oc = &g_out3[c * F];
                }
                #pragma unroll
                for (int q = 0; q < 4; q++) {
                    float4 hv = hr[q];
                    red_add_v4(oc + 4 * q, norm * hv.x, norm * hv.y, norm * hv.z, norm * hv.w);
                }
            }
        }
    }
    gsync();

    // ================= merged P3 + FC1 =================
    {
        float npw = pw_norm(pw3);
        for (int i = tid; i < 176; i += BLOCK)
            s_keys[i] = score_key(g_out3, b3, pw3, npw, i);
        __syncthreads();
        for (int i = wid; i < 176; i += 16) {
            unsigned long long ki = s_keys[i];
            int cnt = 0;
            for (int j = lane; j < 176; j += 32) cnt += (s_keys[j] < ki) ? 1 : 0;
            int rank = __reduce_add_sync(0xFFFFFFFFu, cnt);
            if (rank < 88 && lane == 0) { s_perm[rank] = (short)i; s_val[rank] = key_val(ki); }
        }
        __syncthreads();

        const int i0 = bx * 11;
        float vin[11];
        #pragma unroll
        for (int q = 0; q < 11; q++) {
            int i = i0 + q, j = i >> 4, f = i & 15;
            float v = g_out3[s_perm[j] * F + f] + b3[f];
            v = v > 0.0f ? v : 0.0f;
            vin[q] = v * s_val[j];
        }
        for (int o = tid; o < 1024; o += BLOCK) {
            float acc = 0.0f;
            #pragma unroll
            for (int q = 0; q < 11; q++) acc += vin[q] * fw1[(i0 + q) * 1024 + o];
            atomicAdd(&g_h1[o], acc);
        }
    }
    gsync();

    // ================= final FC: out = h1[1025] @ W23 (bias pre-seeded) =================
    if (gtid < 96 * 64) {
        int j = gtid % 96, ch = gtid / 96;    // 64 chunks of 16 (last has 17)
        int i0 = ch * 16;
        int len = (ch == 63) ? 17 : 16;
        float acc = 0.0f;
        for (int q = 0; q < len; q++) acc += g_h1[i0 + q] * g_W23[(i0 + q) * 96 + j];
        atomicAdd(&out[j], acc);
    }
}

extern "C" void kernel_launch(void* const* d_in, const int* in_sizes, int n_in,
                              void* d_out, int out_size) {
    gcn_fused<<<GRID, BLOCK>>>(
        (const float*)d_in[0],  (const int*)d_in[1],
        (const float*)d_in[3],  (const float*)d_in[4],
        (const float*)d_in[5],  (const float*)d_in[6],
        (const float*)d_in[7],  (const float*)d_in[8],
        (const float*)d_in[9],  (const float*)d_in[10],
        (const float*)d_in[11], (const float*)d_in[12],
        (const float*)d_in[13], (const float*)d_in[14],
        (const float*)d_in[15], (const float*)d_in[16],
        (const float*)d_in[17], (const float*)d_in[18],
        (const float*)d_in[19], (const float*)d_in[20],
        (float*)d_out);
}

// round 14
// speedup vs baseline: 1.1643x; 1.1643x over previous
#include <cuda_runtime.h>
#include <math.h>

#define F      16
#define E0C    90112
#define N0C    1408
#define GRID   128
#define BLOCK  512
#define NT     (GRID * BLOCK)
#define CAP2   8192
#define CAP3   2560

// ---- dynamic smem layout (bytes) ----
#define OFF_KEYS   0        // u64[1408]  = 11264
#define OFF_E2     11264    // u32[8192]  = 32768
#define OFF_H23    44032    // f32[5632]  = 22528 (h2 in merged1, h3 overlay in merged2)
#define OFF_E3     66560    // u32[2560]  = 10240
#define OFF_POS1   76800    // s16[704]
#define OFF_PERM1  78208    // s16[352]
#define OFF_VAL1   78912    // f32[352]
#define OFF_DEG2   80320    // f32[352]
#define OFF_POS2   81728    // s16[352]
#define OFF_PERM2  82432    // s16[176]
#define OFF_VAL2   82784    // f32[176]
#define OFF_DEG3   83488    // f32[176]
#define OFF_MISC   84192    // i32[4]  ([1]=C2 count, [2]=C3 count)
#define SMEM_TOTAL 84992

// ---------------- persistent device state ----------------
__device__ unsigned int g_arrive;
__device__ unsigned int g_gen;
__device__ int g_c1;
__device__ __align__(16) float g_h   [N0C * F];
__device__ __align__(16) float g_outA[N0C * F];   // O_0, reused as O_2 (first 352*16)
__device__ __align__(16) float g_outB[704 * F];   // O_1
__device__ __align__(16) float g_out3[176 * F];   // O_3
__device__ float g_deg0[N0C];
__device__ float g_deg1[704];
__device__ int   g_pos [N0C];
__device__ int2  g_e0[E0C];
__device__ int2  g_e1[E0C];
__device__ float g_h1[1024];
__device__ float g_h2[512];

// ---------------- flat grid barrier (R4-proven) ----------------
__device__ __forceinline__ void gsync() {
    __syncthreads();
    if (threadIdx.x == 0) {
        unsigned int gen;
        asm volatile("ld.acquire.gpu.u32 %0, [%1];" : "=r"(gen) : "l"(&g_gen) : "memory");
        unsigned int old;
        asm volatile("atom.add.release.gpu.u32 %0, [%1], 1;"
                     : "=r"(old) : "l"(&g_arrive) : "memory");
        if (old == GRID - 1u) {
            asm volatile("st.relaxed.gpu.u32 [%0], 0;" :: "l"(&g_arrive) : "memory");
            asm volatile("st.release.gpu.u32 [%0], %1;" :: "l"(&g_gen), "r"(gen + 1u) : "memory");
        } else {
            unsigned int cur;
            do {
                asm volatile("ld.acquire.gpu.u32 %0, [%1];" : "=r"(cur) : "l"(&g_gen) : "memory");
            } while (cur == gen);
        }
    }
    __syncthreads();
}

__device__ __forceinline__ void red_add_v4(float* addr, float a, float b, float c, float d) {
    asm volatile("red.global.add.v4.f32 [%0], {%1, %2, %3, %4};"
                 :: "l"(addr), "f"(a), "f"(b), "f"(c), "f"(d) : "memory");
}

__device__ __forceinline__ unsigned long long score_key(const float* __restrict__ outL,
                                                        const float* __restrict__ bb,
                                                        const float* __restrict__ pw,
                                                        float npw, int i) {
    float s = 0.0f;
    #pragma unroll
    for (int f = 0; f < F; f++) {
        float v = outL[i * F + f] + bb[f];
        v = v > 0.0f ? v : 0.0f;
        s += v * pw[f];
    }
    float sc = tanhf(s / npw);
    int bits = __float_as_int(sc);
    unsigned int ka = (bits >= 0) ? (0x80000000u + (unsigned int)bits)
                                  : ~(unsigned int)bits;
    return ((unsigned long long)(~ka) << 32) | (unsigned int)i;
}

__device__ __forceinline__ float key_val(unsigned long long key) {
    unsigned int ka = ~(unsigned int)(key >> 32);
    int bits = (ka >= 0x80000000u) ? (int)(ka - 0x80000000u) : (int)(~ka);
    return __int_as_float(bits);
}

__device__ __forceinline__ float pw_norm(const float* __restrict__ pw) {
    float npw = 0.0f;
    #pragma unroll
    for (int f = 0; f < F; f++) { float v = pw[f]; npw += v * v; }
    return sqrtf(npw);
}

// distributed scatter: self-loops + edges, RED into global accum
__device__ __forceinline__ void scatter_g(const float* __restrict__ h,
                                          const int2* __restrict__ el, int C,
                                          const float* __restrict__ deg,
                                          float* __restrict__ ob, int n, int gtid) {
    for (int t = gtid; t < n + C; t += NT) {
        const float4* hr; float* oc; float norm;
        if (t < n) {
            norm = 1.0f / (deg[t] + 1.0f);
            hr = (const float4*)&h[t * F]; oc = &ob[t * F];
        } else {
            int2 rc = el[t - n];
            norm = __frsqrt_rn(deg[rc.x] + 1.0f) * __frsqrt_rn(deg[rc.y] + 1.0f);
            hr = (const float4*)&h[rc.x * F]; oc = &ob[rc.y * F];
        }
        #pragma unroll
        for (int q = 0; q < 4; q++) {
            float4 hv = hr[q];
            red_add_v4(oc + 4 * q, norm * hv.x, norm * hv.y, norm * hv.z, norm * hv.w);
        }
    }
}

__global__ void __launch_bounds__(BLOCK, 1) gcn_fused(
    const float* __restrict__ x, const int* __restrict__ ei,
    const float* __restrict__ W0, const float* __restrict__ b0,
    const float* __restrict__ W1, const float* __restrict__ b1,
    const float* __restrict__ W2, const float* __restrict__ b2,
    const float* __restrict__ W3, const float* __restrict__ b3,
    const float* __restrict__ pw0, const float* __restrict__ pw1,
    const float* __restrict__ pw2, const float* __restrict__ pw3,
    const float* __restrict__ fw1, const float* __restrict__ fb1,
    const float* __restrict__ fw2, const float* __restrict__ fb2,
    const float* __restrict__ fw3, const float* __restrict__ fb3,
    float* __restrict__ out)
{
    extern __shared__ __align__(16) char smem[];
    unsigned long long* s_keys = (unsigned long long*)(smem + OFF_KEYS);
    unsigned int* s_e2   = (unsigned int*)(smem + OFF_E2);
    float* s_h2          = (float*)(smem + OFF_H23);
    float* s_h3          = (float*)(smem + OFF_H23);
    unsigned int* s_e3   = (unsigned int*)(smem + OFF_E3);
    short* s_pos1        = (short*)(smem + OFF_POS1);
    short* s_perm1       = (short*)(smem + OFF_PERM1);
    float* s_val1        = (float*)(smem + OFF_VAL1);
    float* s_deg2        = (float*)(smem + OFF_DEG2);
    short* s_pos2        = (short*)(smem + OFF_POS2);
    short* s_perm2       = (short*)(smem + OFF_PERM2);
    float* s_val2        = (float*)(smem + OFF_VAL2);
    float* s_deg3        = (float*)(smem + OFF_DEG3);
    int*   s_misc        = (int*)(smem + OFF_MISC);

    const int tid  = threadIdx.x;
    const int gtid = blockIdx.x * BLOCK + tid;
    const int lane = tid & 31;
    const int wid  = tid >> 5;
    const int bx   = blockIdx.x;

    // ================= Phase M (balanced gemm/edge split; verified in R13) =================
    if (gtid < N0C * F) {             // 22528 gemm tasks, one per thread
        int i = gtid >> 4, j = gtid & 15;
        const float* xr = x + i * 128;
        float acc = 0.0f;
        #pragma unroll 16
        for (int k = 0; k < 128; k++) acc += xr[k] * W0[k * F + j];
        g_h[gtid] = acc;
        g_outA[gtid] = 0.0f;
    }
    if (gtid >= N0C * F) {            // 43008 threads x 2 edges = 86016
        int e = 2 * (gtid - N0C * F);
        #pragma unroll
        for (int q = 0; q < 2; q++) {
            int r = ei[e + q], c = ei[E0C + e + q];
            g_e0[e + q] = make_int2(r, c);
            atomicAdd(&g_deg0[c], 1.0f);
        }
    } else if (gtid < 4096) {         // 4096-edge tail
        int e = 86016 + gtid;
        int r = ei[e], c = ei[E0C + e];
        g_e0[e] = make_int2(r, c);
        atomicAdd(&g_deg0[c], 1.0f);
    }
    if (gtid < 1024) g_h1[gtid] = fb1[gtid];
    if (gtid < 512)  g_h2[gtid] = fb2[gtid];
    if (gtid < 96)   out[gtid]  = fb3[gtid];
    if (gtid == 0)   g_c1 = 0;
    gsync();

    // ================= S0 =================
    scatter_g(g_h, g_e0, E0C, g_deg0, g_outA, N0C, gtid);
    gsync();

    // ================= P0 (distributed pool; h1 gather+gemm; zero outB; clean deg0) =======
    {
        for (int i = gtid; i < N0C; i += NT) g_deg0[i] = 0.0f;
        float npw = pw_norm(pw0);
        for (int i = tid; i < N0C; i += BLOCK)
            s_keys[i] = score_key(g_outA, b0, pw0, npw, i);
        __syncthreads();
        int i = bx * (BLOCK / 32) + wid;
        if (i < N0C) {
            unsigned long long ki = s_keys[i];
            int cnt = 0;
            for (int j = lane; j < N0C; j += 32) cnt += (s_keys[j] < ki) ? 1 : 0;
            int rank = __reduce_add_sync(0xFFFFFFFFu, cnt);
            if (rank < 704) {
                float val = key_val(ki);
                if (lane == 0) g_pos[i] = rank;
                if (lane < F) {
                    float acc = 0.0f;
                    #pragma unroll
                    for (int f = 0; f < F; f++) {
                        float v = g_outA[i * F + f] + b0[f];
                        v = v > 0.0f ? v : 0.0f;
                        acc += v * W1[f * F + lane];
                    }
                    g_h[rank * F + lane] = acc * val;
                    g_outB[rank * F + lane] = 0.0f;
                }
            } else if (lane == 0) {
                g_pos[i] = -1;
            }
        }
    }
    gsync();

    // ================= E0 (remap 90k -> g_e1 + deg1) =================
    {
        int iters = (E0C + NT - 1) / NT;
        for (int it = 0; it < iters; it++) {
            int e = it * NT + gtid;
            bool valid = false; int nr = 0, nc = 0;
            if (e < E0C) {
                int2 rc = g_e0[e];
                nr = g_pos[rc.x]; nc = g_pos[rc.y];
                valid = (nr >= 0) && (nc >= 0);
            }
            unsigned int m = __ballot_sync(0xFFFFFFFFu, valid);
            if (m) {
                int leader = __ffs(m) - 1;
                int base = 0;
                if (lane == leader) base = atomicAdd(&g_c1, __popc(m));
                base = __shfl_sync(0xFFFFFFFFu, base, leader);
                if (valid) {
                    int pp = base + __popc(m & ((1u << lane) - 1u));
                    g_e1[pp] = make_int2(nr, nc);
                    atomicAdd(&g_deg1[nc], 1.0f);
                }
            }
        }
    }
    gsync();

    // ================= S1 (scatter layer1; zero O2 region of outA) =================
    {
        int C1 = g_c1;
        scatter_g(g_h, g_e1, C1, g_deg1, g_outB, 704, gtid);
        if (gtid < 352 * F) g_outA[gtid] = 0.0f;
    }
    gsync();

    // ================= MERGED1: P1 + E1 + S2 (redundant per block) =================
    {
        for (int i = gtid; i < 704; i += NT) g_deg1[i] = 0.0f;   // replay clean
        if (gtid < 176 * F) g_out3[gtid] = 0.0f;                 // O3 zero for merged2

        // a) rank all 704 nodes locally
        float npw = pw_norm(pw1);
        for (int i = tid; i < 704; i += BLOCK)
            s_keys[i] = score_key(g_outB, b1, pw1, npw, i);
        if (tid < 352) s_deg2[tid] = 0.0f;
        if (tid == 0) s_misc[1] = 0;
        __syncthreads();
        for (int i = wid; i < 704; i += 16) {
            unsigned long long ki = s_keys[i];
            int cnt = 0;
            for (int j = lane; j < 704; j += 32) cnt += (s_keys[j] < ki) ? 1 : 0;
            int rank = __reduce_add_sync(0xFFFFFFFFu, cnt);
            if (lane == 0) {
                if (rank < 352) {
                    s_pos1[i] = (short)rank;
                    s_perm1[rank] = (short)i;
                    s_val1[rank] = key_val(ki);
                } else s_pos1[i] = -1;
            }
        }
        __syncthreads();

        // b) single-pass compact g_e1[0..C1) -> s_e2 + smem degrees
        int C1 = g_c1;
        int iters = (C1 + BLOCK - 1) / BLOCK;
        for (int it = 0; it < iters; it++) {
            int e = it * BLOCK + tid;
            bool valid = false; short nr = 0, nc = 0;
            if (e < C1) {
                int2 rc = g_e1[e];
                nr = s_pos1[rc.x]; nc = s_pos1[rc.y];
                valid = (nr >= 0) && (nc >= 0);
            }
            unsigned int m = __ballot_sync(0xFFFFFFFFu, valid);
            if (m) {
                int leader = __ffs(m) - 1;
                int base = 0;
                if (lane == leader) base = atomicAdd(&s_misc[1], __popc(m));
                base = __shfl_sync(0xFFFFFFFFu, base, leader);
                if (valid) {
                    int pp = base + __popc(m & ((1u << lane) - 1u));
                    if (pp < CAP2)
                        s_e2[pp] = (unsigned int)(unsigned short)nr |
                                   ((unsigned int)(unsigned short)nc << 16);
                    atomicAdd(&s_deg2[nc], 1.0f);
                }
            }
        }
        __syncthreads();
        int C2 = min(s_misc[1], CAP2);

        // c) h2 = X1 @ W2 (warp shfl-gemm) into smem
        {
            float w[16];
            int f2 = lane & 15;
            #pragma unroll
            for (int f = 0; f < 16; f++) w[f] = W2[f * F + f2];
            int sub = lane >> 4;
            for (int j0 = wid * 2; j0 < 352; j0 += 32) {
                int j = j0 + sub;
                int p = s_perm1[j];
                float val = s_val1[j];
                int f = lane & 15;
                float v = g_outB[p * F + f] + b1[f];
                v = v > 0.0f ? v : 0.0f;
                float acc = 0.0f;
                #pragma unroll
                for (int fk = 0; fk < 16; fk++)
                    acc += __shfl_sync(0xFFFFFFFFu, v, (sub << 4) + fk) * w[fk];
                s_h2[j * F + f2] = acc * val;
            }
        }
        __syncthreads();

        // d) scatter this block's slice (thread-partitioned) into global O2 (=outA)
        {
            int total = 352 + C2;
            int chunk = (total + GRID - 1) / GRID;
            int t0 = bx * chunk, t1 = min(t0 + chunk, total);
            for (int t = t0 + tid; t < t1; t += BLOCK) {
                const float4* hr; float* oc; float norm;
                if (t < 352) {
                    norm = 1.0f / (s_deg2[t] + 1.0f);
                    hr = (const float4*)&s_h2[t * F]; oc = &g_outA[t * F];
                } else {
                    unsigned int pk = s_e2[t - 352];
                    int r = pk & 0xFFFF, c = pk >> 16;
                    norm = __frsqrt_rn(s_deg2[r] + 1.0f) * __frsqrt_rn(s_deg2[c] + 1.0f);
                    hr = (const float4*)&s_h2[r * F]; oc = &g_outA[c * F];
                }
                #pragma unroll
                for (int q = 0; q < 4; q++) {
                    float4 hv = hr[q];
                    red_add_v4(oc + 4 * q, norm * hv.x, norm * hv.y, norm * hv.z, norm * hv.w);
                }
            }
        }
    }
    gsync();

    // ================= MERGED2: P2 + E2 + S3 (redundant; edges from smem) =================
    {
        // a) rank all 352 nodes from O2
        float npw = pw_norm(pw2);
        for (int i = tid; i < 352; i += BLOCK)
            s_keys[i] = score_key(g_outA, b2, pw2, npw, i);
        if (tid < 176) s_deg3[tid] = 0.0f;
        if (tid == 0) s_misc[2] = 0;
        __syncthreads();
        for (int i = wid; i < 352; i += 16) {
            unsigned long long ki = s_keys[i];
            int cnt = 0;
            for (int j = lane; j < 352; j += 32) cnt += (s_keys[j] < ki) ? 1 : 0;
            int rank = __reduce_add_sync(0xFFFFFFFFu, cnt);
            if (lane == 0) {
                if (rank < 176) {
                    s_pos2[i] = (short)rank;
                    s_perm2[rank] = (short)i;
                    s_val2[rank] = key_val(ki);
                } else s_pos2[i] = -1;
            }
        }
        __syncthreads();

        // b) compact s_e2[0..C2) -> s_e3 + s_deg3 (smem->smem)
        int C2 = min(s_misc[1], CAP2);
        int iters = (C2 + BLOCK - 1) / BLOCK;
        for (int it = 0; it < iters; it++) {
            int e = it * BLOCK + tid;
            bool valid = false; short nr = 0, nc = 0;
            if (e < C2) {
                unsigned int pk = s_e2[e];
                nr = s_pos2[pk & 0xFFFF]; nc = s_pos2[pk >> 16];
                valid = (nr >= 0) && (nc >= 0);
            }
            unsigned int m = __ballot_sync(0xFFFFFFFFu, valid);
            if (m) {
                int leader = __ffs(m) - 1;
                int base = 0;
                if (lane == leader) base = atomicAdd(&s_misc[2], __popc(m));
                base = __shfl_sync(0xFFFFFFFFu, base, leader);
                if (valid) {
                    int pp = base + __popc(m & ((1u << lane) - 1u));
                    if (pp < CAP3)
                        s_e3[pp] = (unsigned int)(unsigned short)nr |
                                   ((unsigned int)(unsigned short)nc << 16);
                    atomicAdd(&s_deg3[nc], 1.0f);
                }
            }
        }
        __syncthreads();
        int C3 = min(s_misc[2], CAP3);

        // c) h3 = X2 @ W3 into smem (overlays dead s_h2)
        {
            float w[16];
            int f2 = lane & 15;
            #pragma unroll
            for (int f = 0; f < 16; f++) w[f] = W3[f * F + f2];
            int sub = lane >> 4;
            for (int j0 = wid * 2; j0 < 176; j0 += 32) {
                int j = j0 + sub;
                int p = s_perm2[j];
                float val = s_val2[j];
                int f = lane & 15;
                float v = g_outA[p * F + f] + b2[f];
                v = v > 0.0f ? v : 0.0f;
                float acc = 0.0f;
                #pragma unroll
                for (int fk = 0; fk < 16; fk++)
                    acc += __shfl_sync(0xFFFFFFFFu, v, (sub << 4) + fk) * w[fk];
                s_h3[j * F + f2] = acc * val;
            }
        }
        __syncthreads();

        // d) scatter this block's slice (thread-partitioned) into global O3
        {
            int total = 176 + C3;
            int chunk = (total + GRID - 1) / GRID;
            int t0 = bx * chunk, t1 = min(t0 + chunk, total);
            for (int t = t0 + tid; t < t1; t += BLOCK) {
                const float4* hr; float* oc; float norm;
                if (t < 176) {
                    norm = 1.0f / (s_deg3[t] + 1.0f);
                    hr = (const float4*)&s_h3[t * F]; oc = &g_out3[t * F];
                } else {
                    unsigned int pk = s_e3[t - 176];
                    int r = pk & 0xFFFF, c = pk >> 16;
                    norm = __frsqrt_rn(s_deg3[r] + 1.0f) * __frsqrt_rn(s_deg3[c] + 1.0f);
                    hr = (const float4*)&s_h3[r * F]; oc = &g_out3[c * F];
                }
                #pragma unroll
                for (int q = 0; q < 4; q++) {
                    float4 hv = hr[q];
                    red_add_v4(oc + 4 * q, norm * hv.x, norm * hv.y, norm * hv.z, norm * hv.w);
                }
            }
        }
    }
    gsync();

    // ================= merged P3 + FC1 =================
    {
        float npw = pw_norm(pw3);
        for (int i = tid; i < 176; i += BLOCK)
            s_keys[i] = score_key(g_out3, b3, pw3, npw, i);
        __syncthreads();
        for (int i = wid; i < 176; i += 16) {
            unsigned long long ki = s_keys[i];
            int cnt = 0;
            for (int j = lane; j < 176; j += 32) cnt += (s_keys[j] < ki) ? 1 : 0;
            int rank = __reduce_add_sync(0xFFFFFFFFu, cnt);
            if (rank < 88 && lane == 0) { s_perm2[rank] = (short)i; s_val2[rank] = key_val(ki); }
        }
        __syncthreads();

        const int i0 = bx * 11;
        float vin[11];
        #pragma unroll
        for (int q = 0; q < 11; q++) {
            int i = i0 + q, j = i >> 4, f = i & 15;
            float v = g_out3[s_perm2[j] * F + f] + b3[f];
            v = v > 0.0f ? v : 0.0f;
            vin[q] = v * s_val2[j];
        }
        for (int o = tid; o < 1024; o += BLOCK) {
            float acc = 0.0f;
            #pragma unroll
            for (int q = 0; q < 11; q++) acc += vin[q] * fw1[(i0 + q) * 1024 + o];
            atomicAdd(&g_h1[o], acc);
        }
    }
    gsync();

    // ================= FC2 =================
    {
        int j = gtid & 511, ch = gtid >> 9;   // 128 chunks of 8
        int i0 = ch * 8;
        float acc = 0.0f;
        #pragma unroll
        for (int i = 0; i < 8; i++) acc += g_h1[i0 + i] * fw2[(i0 + i) * 512 + j];
        atomicAdd(&g_h2[j], acc);
    }
    gsync();

    // ================= FC3 =================
    if (gtid < 96 * 64) {
        int j = gtid % 96, ch = gtid / 96;    // 64 chunks of 8
        int i0 = ch * 8;
        float acc = 0.0f;
        #pragma unroll
        for (int i = 0; i < 8; i++) acc += g_h2[i0 + i] * fw3[(i0 + i) * 96 + j];
        atomicAdd(&out[j], acc);
    }
}

extern "C" void kernel_launch(void* const* d_in, const int* in_sizes, int n_in,
                              void* d_out, int out_size) {
    cudaFuncSetAttribute(gcn_fused, cudaFuncAttributeMaxDynamicSharedMemorySize, SMEM_TOTAL);
    gcn_fused<<<GRID, BLOCK, SMEM_TOTAL>>>(
        (const float*)d_in[0],  (const int*)d_in[1],
        (const float*)d_in[3],  (const float*)d_in[4],
        (const float*)d_in[5],  (const float*)d_in[6],
        (const float*)d_in[7],  (const float*)d_in[8],
        (const float*)d_in[9],  (const float*)d_in[10],
        (const float*)d_in[11], (const float*)d_in[12],
        (const float*)d_in[13], (const float*)d_in[14],
        (const float*)d_in[15], (const float*)d_in[16],
        (const float*)d_in[17], (const float*)d_in[18],
        (const float*)d_in[19], (const float*)d_in[20],
        (float*)d_out);
}

// round 15
// speedup vs baseline: 1.7656x; 1.5165x over previous
#include <cuda_runtime.h>
#include <math.h>

#define F      16
#define E0C    90112
#define N0C    1408
#define GRID   128
#define BLOCK  512
#define NT     (GRID * BLOCK)
#define CAP3   2560

// ---------------- persistent device state ----------------
__device__ unsigned int g_arrive;
__device__ unsigned int g_gen;             // monotonic generation
__device__ int g_c1, g_c2;                 // compacted edge counts (layers 1,2)
__device__ __align__(16) float g_h   [N0C * F];
__device__ __align__(16) float g_outA[N0C * F];   // O_0, reused as O_2
__device__ __align__(16) float g_outB[704 * F];   // O_1
__device__ __align__(16) float g_out3[176 * F];   // O_3
__device__ float g_deg0[N0C];
__device__ float g_deg1[704];
__device__ float g_deg2[352];
__device__ int   g_pos [N0C];
__device__ int2  g_e0[E0C];
__device__ int2  g_e1[E0C];
__device__ int2  g_e2[E0C];
__device__ float g_h1[1024];

// ---------------- flat grid barrier (R4-proven) ----------------
__device__ __forceinline__ void gsync() {
    __syncthreads();
    if (threadIdx.x == 0) {
        unsigned int gen;
        asm volatile("ld.acquire.gpu.u32 %0, [%1];" : "=r"(gen) : "l"(&g_gen) : "memory");
        unsigned int old;
        asm volatile("atom.add.release.gpu.u32 %0, [%1], 1;"
                     : "=r"(old) : "l"(&g_arrive) : "memory");
        if (old == GRID - 1u) {
            asm volatile("st.relaxed.gpu.u32 [%0], 0;" :: "l"(&g_arrive) : "memory");
            asm volatile("st.release.gpu.u32 [%0], %1;" :: "l"(&g_gen), "r"(gen + 1u) : "memory");
        } else {
            unsigned int cur;
            do {
                asm volatile("ld.acquire.gpu.u32 %0, [%1];" : "=r"(cur) : "l"(&g_gen) : "memory");
            } while (cur == gen);
        }
    }
    __syncthreads();
}

__device__ __forceinline__ void red_add_v4(float* addr, float a, float b, float c, float d) {
    asm volatile("red.global.add.v4.f32 [%0], {%1, %2, %3, %4};"
                 :: "l"(addr), "f"(a), "f"(b), "f"(c), "f"(d) : "memory");
}

__device__ __forceinline__ unsigned long long score_key(const float* __restrict__ outL,
                                                        const float* __restrict__ bb,
                                                        const float* __restrict__ pw,
                                                        float npw, int i) {
    float s = 0.0f;
    #pragma unroll
    for (int f = 0; f < F; f++) {
        float v = outL[i * F + f] + bb[f];
        v = v > 0.0f ? v : 0.0f;
        s += v * pw[f];
    }
    float sc = tanhf(s / npw);
    int bits = __float_as_int(sc);
    unsigned int ka = (bits >= 0) ? (0x80000000u + (unsigned int)bits)
                                  : ~(unsigned int)bits;
    return ((unsigned long long)(~ka) << 32) | (unsigned int)i;
}

__device__ __forceinline__ float key_val(unsigned long long key) {
    unsigned int ka = ~(unsigned int)(key >> 32);
    int bits = (ka >= 0x80000000u) ? (int)(ka - 0x80000000u) : (int)(~ka);
    return __int_as_float(bits);
}

__device__ __forceinline__ float pw_norm(const float* __restrict__ pw) {
    float npw = 0.0f;
    #pragma unroll
    for (int f = 0; f < F; f++) { float v = pw[f]; npw += v * v; }
    return sqrtf(npw);
}

// distributed scatter: self-loops + edges, RED into global accum
__device__ __forceinline__ void scatter_g(const float* __restrict__ h,
                                          const int2* __restrict__ el, int C,
                                          const float* __restrict__ deg,
                                          float* __restrict__ ob, int n, int gtid) {
    for (int t = gtid; t < n + C; t += NT) {
        const float4* hr; float* oc; float norm;
        if (t < n) {
            norm = 1.0f / (deg[t] + 1.0f);
            hr = (const float4*)&h[t * F]; oc = &ob[t * F];
        } else {
            int2 rc = el[t - n];
            norm = __frsqrt_rn(deg[rc.x] + 1.0f) * __frsqrt_rn(deg[rc.y] + 1.0f);
            hr = (const float4*)&h[rc.x * F]; oc = &ob[rc.y * F];
        }
        #pragma unroll
        for (int q = 0; q < 4; q++) {
            float4 hv = hr[q];
            red_add_v4(oc + 4 * q, norm * hv.x, norm * hv.y, norm * hv.z, norm * hv.w);
        }
    }
}

// distributed pool: rank own warp's node, fused gather+gemm into hdst, zero outN
__device__ __forceinline__ void pool_dist(const float* __restrict__ outL,
                                          const float* __restrict__ bb,
                                          const float* __restrict__ pw,
                                          const float* __restrict__ Wn,
                                          float* __restrict__ outN,
                                          float* __restrict__ hdst,
                                          int n, int K,
                                          unsigned long long* s_keys,
                                          int tid, int lane, int wid, int bx) {
    if (bx * (BLOCK / 32) >= n) return;
    float npw = pw_norm(pw);
    for (int i = tid; i < n; i += BLOCK) s_keys[i] = score_key(outL, bb, pw, npw, i);
    __syncthreads();
    int i = bx * (BLOCK / 32) + wid;
    if (i < n) {
        unsigned long long ki = s_keys[i];
        int cnt = 0;
        for (int j = lane; j < n; j += 32) cnt += (s_keys[j] < ki) ? 1 : 0;
        int rank = __reduce_add_sync(0xFFFFFFFFu, cnt);
        if (rank < K) {
            float val = key_val(ki);
            if (lane == 0) g_pos[i] = rank;
            if (lane < F) {
                float acc = 0.0f;
                #pragma unroll
                for (int f = 0; f < F; f++) {
                    float v = outL[i * F + f] + bb[f];
                    v = v > 0.0f ? v : 0.0f;
                    acc += v * Wn[f * F + lane];
                }
                hdst[rank * F + lane] = acc * val;
                outN[rank * F + lane] = 0.0f;
            }
        } else if (lane == 0) {
            g_pos[i] = -1;
        }
    }
    __syncthreads();
}

// distributed edge remap + compact + degree
__device__ __forceinline__ void remap_dist(const int2* __restrict__ ein, int C,
                                           int2* __restrict__ eout, int* pcnt,
                                           float* __restrict__ degout,
                                           int gtid, int lane) {
    int iters = (C + NT - 1) / NT;
    for (int it = 0; it < iters; it++) {
        int e = it * NT + gtid;
        bool valid = false; int nr = 0, nc = 0;
        if (e < C) {
            int2 rc = ein[e];
            nr = g_pos[rc.x]; nc = g_pos[rc.y];
            valid = (nr >= 0) && (nc >= 0);
        }
        unsigned int m = __ballot_sync(0xFFFFFFFFu, valid);
        if (m) {
            int leader = __ffs(m) - 1;
            int base = 0;
            if (lane == leader) base = atomicAdd(pcnt, __popc(m));
            base = __shfl_sync(0xFFFFFFFFu, base, leader);
            if (valid) {
                int pp = base + __popc(m & ((1u << lane) - 1u));
                eout[pp] = make_int2(nr, nc);
                atomicAdd(&degout[nc], 1.0f);
            }
        }
    }
}

__global__ void __launch_bounds__(BLOCK, 1) gcn_fused(
    const float* __restrict__ x, const int* __restrict__ ei,
    const float* __restrict__ W0, const float* __restrict__ b0,
    const float* __restrict__ W1, const float* __restrict__ b1,
    const float* __restrict__ W2, const float* __restrict__ b2,
    const float* __restrict__ W3, const float* __restrict__ b3,
    const float* __restrict__ pw0, const float* __restrict__ pw1,
    const float* __restrict__ pw2, const float* __restrict__ pw3,
    const float* __restrict__ fw1, const float* __restrict__ fb1,
    const float* __restrict__ fw2, const float* __restrict__ fb2,
    const float* __restrict__ fw3, const float* __restrict__ fb3,
    float* __restrict__ out)
{
    const int tid  = threadIdx.x;
    const int gtid = blockIdx.x * BLOCK + tid;
    const int lane = tid & 31;
    const int wid  = tid >> 5;
    const int bx   = blockIdx.x;

    __shared__ __align__(16) unsigned long long s_keys[N0C];  // 11.3 KB
    __shared__ __align__(16) float s_h3[176 * F];             // 11.3 KB
    __shared__ unsigned int s_e3[CAP3];                       // 10.2 KB
    __shared__ short  s_pos2[352];
    __shared__ short  s_perm[176];
    __shared__ float  s_val [176];
    __shared__ float  s_deg3[176];
    __shared__ int    s_scan[17];

    // ================= Phase M (balanced gemm/edge split; validated in R13 run) ==========
    if (gtid < N0C * F) {             // 22528 gemm tasks, one per thread
        int i = gtid >> 4, j = gtid & 15;
        const float* xr = x + i * 128;
        float acc = 0.0f;
        #pragma unroll 16
        for (int k = 0; k < 128; k++) acc += xr[k] * W0[k * F + j];
        g_h[gtid] = acc;
        g_outA[gtid] = 0.0f;
    }
    if (gtid >= N0C * F) {            // 43008 threads x 2 edges = 86016
        int e = 2 * (gtid - N0C * F);
        #pragma unroll
        for (int q = 0; q < 2; q++) {
            int r = ei[e + q], c = ei[E0C + e + q];
            g_e0[e + q] = make_int2(r, c);
            atomicAdd(&g_deg0[c], 1.0f);
        }
    } else if (gtid < 4096) {         // 4096-edge tail
        int e = 86016 + gtid;
        int r = ei[e], c = ei[E0C + e];
        g_e0[e] = make_int2(r, c);
        atomicAdd(&g_deg0[c], 1.0f);
    }
    if (gtid < 1024) g_h1[gtid] = fb1[gtid];
    if (gtid < 96)   out[gtid]  = fb3[gtid];
    if (gtid == 0) { g_c1 = 0; g_c2 = 0; }
    gsync();

    // ================= S0 =================
    scatter_g(g_h, g_e0, E0C, g_deg0, g_outA, N0C, gtid);
    gsync();

    // ================= P0 (+ clean deg0) =================
    for (int i = gtid; i < N0C; i += NT) g_deg0[i] = 0.0f;
    pool_dist(g_outA, b0, pw0, W1, g_outB, g_h, N0C, 704, s_keys, tid, lane, wid, bx);
    gsync();

    // ================= E0 =================
    remap_dist(g_e0, E0C, g_e1, &g_c1, g_deg1, gtid, lane);
    gsync();

    // ================= S1 =================
    {
        int C1 = g_c1;
        scatter_g(g_h, g_e1, C1, g_deg1, g_outB, 704, gtid);
    }
    gsync();

    // ================= P1 (+ clean deg1) =================
    for (int i = gtid; i < 704; i += NT) g_deg1[i] = 0.0f;
    pool_dist(g_outB, b1, pw1, W2, g_outA, g_h, 704, 352, s_keys, tid, lane, wid, bx);
    gsync();

    // ================= E1 =================
    {
        int C1 = g_c1;
        remap_dist(g_e1, C1, g_e2, &g_c2, g_deg2, gtid, lane);
    }
    gsync();

    // ================= S2 (+ zero O3) =================
    {
        int C2 = g_c2;
        scatter_g(g_h, g_e2, C2, g_deg2, g_outA, 352, gtid);
        if (gtid < 176 * F) g_out3[gtid] = 0.0f;
    }
    gsync();

    // ================= merged P2+E2+S3 (redundant per block; deterministic scan) =========
    {
        for (int i = gtid; i < 352; i += NT) g_deg2[i] = 0.0f;   // self-clean

        // a) rank all 352 nodes locally
        float npw = pw_norm(pw2);
        for (int i = tid; i < 352; i += BLOCK)
            s_keys[i] = score_key(g_outA, b2, pw2, npw, i);
        if (tid < 176) s_deg3[tid] = 0.0f;
        __syncthreads();
        for (int i = wid; i < 352; i += 16) {
            unsigned long long ki = s_keys[i];
            int cnt = 0;
            for (int j = lane; j < 352; j += 32) cnt += (s_keys[j] < ki) ? 1 : 0;
            int rank = __reduce_add_sync(0xFFFFFFFFu, cnt);
            if (lane == 0) {
                if (rank < 176) {
                    s_pos2[i] = (short)rank;
                    s_perm[rank] = (short)i;
                    s_val[rank] = key_val(ki);
                } else s_pos2[i] = -1;
            }
        }
        __syncthreads();

        // b) deterministic two-pass compaction of g_e2 -> s_e3 (identical in every block)
        int C2 = g_c2;
        int seg = (C2 + BLOCK - 1) / BLOCK;
        int e0 = tid * seg, e1 = min(e0 + seg, C2);
        int mycnt = 0;
        for (int e = e0; e < e1; e++) {
            int2 rc = g_e2[e];
            if (s_pos2[rc.x] >= 0 && s_pos2[rc.y] >= 0) mycnt++;
        }
        int pre = mycnt;
        #pragma unroll
        for (int d = 1; d < 32; d <<= 1) {
            int t = __shfl_up_sync(0xFFFFFFFFu, pre, d);
            if (lane >= d) pre += t;
        }
        if (lane == 31) s_scan[wid] = pre;
        __syncthreads();
        if (tid == 0) {
            int acc = 0;
            #pragma unroll
            for (int w = 0; w < 16; w++) { int t = s_scan[w]; s_scan[w] = acc; acc += t; }
            s_scan[16] = acc;
        }
        __syncthreads();
        int base = s_scan[wid] + (pre - mycnt);
        int C3 = min(s_scan[16], CAP3);
        for (int e = e0; e < e1; e++) {
            int2 rc = g_e2[e];
            short nr = s_pos2[rc.x], nc = s_pos2[rc.y];
            if (nr >= 0 && nc >= 0) {
                if (base < CAP3)
                    s_e3[base] = (unsigned int)(unsigned short)nr |
                                 ((unsigned int)(unsigned short)nc << 16);
                atomicAdd(&s_deg3[nc], 1.0f);
                base++;
            }
        }
        __syncthreads();

        // c) h3 = X2 @ W3 (warp shfl-gemm) into smem
        {
            float w[16];
            int f2 = lane & 15;
            #pragma unroll
            for (int f = 0; f < 16; f++) w[f] = W3[f * F + f2];
            int sub = lane >> 4;
            for (int j0 = wid * 2; j0 < 176; j0 += 32) {
                int j = j0 + sub;
                int p = s_perm[j];
                float val = s_val[j];
                int f = lane & 15;
                float v = g_outA[p * F + f] + b2[f];
                v = v > 0.0f ? v : 0.0f;
                float acc = 0.0f;
                #pragma unroll
                for (int fk = 0; fk < 16; fk++)
                    acc += __shfl_sync(0xFFFFFFFFu, v, (sub << 4) + fk) * w[fk];
                s_h3[j * F + f2] = acc * val;
            }
        }
        __syncthreads();

        // d) scatter this block's slice (thread-partitioned) into global O3
        {
            int total = 176 + C3;
            int chunk = (total + GRID - 1) / GRID;
            int t0 = bx * chunk, t1 = min(t0 + chunk, total);
            for (int t = t0 + tid; t < t1; t += BLOCK) {
                const float4* hr; float* oc; float norm;
                if (t < 176) {
                    norm = 1.0f / (s_deg3[t] + 1.0f);
                    hr = (const float4*)&s_h3[t * F]; oc = &g_out3[t * F];
                } else {
                    unsigned int pk = s_e3[t - 176];
                    int r = pk & 0xFFFF, c = pk >> 16;
                    norm = __frsqrt_rn(s_deg3[r] + 1.0f) * __frsqrt_rn(s_deg3[c] + 1.0f);
                    hr = (const float4*)&s_h3[r * F]; oc = &g_out3[c * F];
                }
                #pragma unroll
                for (int q = 0; q < 4; q++) {
                    float4 hv = hr[q];
                    red_add_v4(oc + 4 * q, norm * hv.x, norm * hv.y, norm * hv.z, norm * hv.w);
                }
            }
        }
    }
    gsync();

    // ================= merged P3 + FC1 =================
    {
        float npw = pw_norm(pw3);
        for (int i = tid; i < 176; i += BLOCK)
            s_keys[i] = score_key(g_out3, b3, pw3, npw, i);
        __syncthreads();
        for (int i = wid; i < 176; i += 16) {
            unsigned long long ki = s_keys[i];
            int cnt = 0;
            for (int j = lane; j < 176; j += 32) cnt += (s_keys[j] < ki) ? 1 : 0;
            int rank = __reduce_add_sync(0xFFFFFFFFu, cnt);
            if (rank < 88 && lane == 0) { s_perm[rank] = (short)i; s_val[rank] = key_val(ki); }
        }
        __syncthreads();

        const int i0 = bx * 11;
        float vin[11];
        #pragma unroll
        for (int q = 0; q < 11; q++) {
            int i = i0 + q, j = i >> 4, f = i & 15;
            float v = g_out3[s_perm[j] * F + f] + b3[f];
            v = v > 0.0f ? v : 0.0f;
            vin[q] = v * s_val[j];
        }
        for (int o = tid; o < 1024; o += BLOCK) {
            float acc = 0.0f;
            #pragma unroll
            for (int q = 0; q < 11; q++) acc += vin[q] * fw1[(i0 + q) * 1024 + o];
            atomicAdd(&g_h1[o], acc);
        }
    }
    gsync();

    // ================= merged FC2+FC3 (one phase; block bx owns h2[4bx..4bx+4)) =========
    {
        __shared__ float s_part[64];    // 16 warps x 4 j-classes
        __shared__ float s_h2loc[4];
        int j4 = tid & 3;               // local j-class 0..3
        int ch = tid >> 2;              // 128 input chunks of 8
        int jq = bx * 4 + j4;           // global h2 index owned by this block
        int i0 = ch * 8;
        float acc = 0.0f;
        #pragma unroll
        for (int q = 0; q < 8; q++) acc += g_h1[i0 + q] * fw2[(i0 + q) * 512 + jq];
        // reduce lanes sharing (lane & 3)
        acc += __shfl_xor_sync(0xFFFFFFFFu, acc, 4);
        acc += __shfl_xor_sync(0xFFFFFFFFu, acc, 8);
        acc += __shfl_xor_sync(0xFFFFFFFFu, acc, 16);
        if (lane < 4) s_part[wid * 4 + lane] = acc;
        __syncthreads();
        if (tid < 4) {
            float s = fb2[bx * 4 + tid];
            #pragma unroll
            for (int w = 0; w < 16; w++) s += s_part[w * 4 + tid];
            s_h2loc[tid] = s;
        }
        __syncthreads();
        if (tid < 96) {
            float acc2 = 0.0f;
            #pragma unroll
            for (int q = 0; q < 4; q++)
                acc2 += s_h2loc[q] * fw3[(bx * 4 + q) * 96 + tid];
            atomicAdd(&out[tid], acc2);
        }
    }
}

extern "C" void kernel_launch(void* const* d_in, const int* in_sizes, int n_in,
                              void* d_out, int out_size) {
    gcn_fused<<<GRID, BLOCK>>>(
        (const float*)d_in[0],  (const int*)d_in[1],
        (const float*)d_in[3],  (const float*)d_in[4],
        (const float*)d_in[5],  (const float*)d_in[6],
        (const float*)d_in[7],  (const float*)d_in[8],
        (const float*)d_in[9],  (const float*)d_in[10],
        (const float*)d_in[11], (const float*)d_in[12],
        (const float*)d_in[13], (const float*)d_in[14],
        (const float*)d_in[15], (const float*)d_in[16],
        (const float*)d_in[17], (const float*)d_in[18],
        (const float*)d_in[19], (const float*)d_in[20],
        (float*)d_out);
}